// round 1
// baseline (speedup 1.0000x reference)
#include <cuda_runtime.h>
#include <cuda_bf16.h>
#include <math.h>

// ---------------------------------------------------------------------------
// SchNet on GB300: distance-table factorization.
// w[i,j,:] depends only on scalar d_ij -> tabulate filter MLP on a d-grid,
// cubic-Lagrange interpolate per pair in the conv. Turns ~90 GFLOP of
// per-pair MLPs into ~0.1 GFLOP table build + L2-resident table lookups.
// ---------------------------------------------------------------------------

#define NATOMS 512
#define FDIM   128
#define KKER   301
#define NLAY   3
#define NGRID  576          // d-grid points; index i represents d = (i-1)/32
#define DSCALE 32.0f        // 1/h
#define NWIN   48           // RBF window (|d - c_k| <= 2 covered)
#define LOG2F_ 0.6931471805599453f

// scratch (static device globals; no allocations anywhere)
__device__ float g_dt[NATOMS * NATOMS];            // t = d*32 + 1 (clamped)
__device__ float g_table[NLAY][NGRID * FDIM];      // filter tables
__device__ float g_h[NATOMS * FDIM];
__device__ float g_o[NATOMS * FDIM];
__device__ float g_cpart[2][NATOMS * FDIM];        // conv partial sums (j-split)
__device__ float g_c1[NATOMS * FDIM];

__device__ __forceinline__ float ssp(float x) {
    // softplus(x) - log(2), numerically stable
    float ax = fabsf(x);
    return fmaxf(x, 0.0f) + log1pf(expf(-ax)) - LOG2F_;
}

// ---------------------------------------------------------------------------
// 1) pairwise scaled distances
// ---------------------------------------------------------------------------
__global__ void dist_kernel(const float* __restrict__ r) {
    int idx = blockIdx.x * blockDim.x + threadIdx.x;   // N*N threads
    int i = idx >> 9, j = idx & 511;
    float dx = r[i * 3 + 0] - r[j * 3 + 0];
    float dy = r[i * 3 + 1] - r[j * 3 + 1];
    float dz = r[i * 3 + 2] - r[j * 3 + 2];
    float d = sqrtf(dx * dx + dy * dy + dz * dz);
    float t = d * DSCALE + 1.0f;
    t = fminf(t, (float)(NGRID - 3));
    g_dt[idx] = t;
}

// ---------------------------------------------------------------------------
// 2) filter tables: for each layer l and grid point, run the filter MLP.
//    4 grid points per block, 128 threads (one per output feature).
// ---------------------------------------------------------------------------
__global__ __launch_bounds__(128) void table_kernel(
    const float* __restrict__ cf_W1, const float* __restrict__ cf_b1,
    const float* __restrict__ cf_W2, const float* __restrict__ cf_b2)
{
    int l  = blockIdx.y;
    int i0 = blockIdx.x * 4;
    int tid = threadIdx.x;

    __shared__ float e_s[4][NWIN];
    __shared__ int   k0_s[4];
    __shared__ float w1_s[4][FDIM];

    if (tid < 4) {
        float d = (float)(i0 + tid - 1) * (1.0f / DSCALE);
        int k0 = (int)ceilf((d - 2.0f) * 10.0f);
        k0 = max(0, min(KKER - NWIN, k0));
        k0_s[tid] = k0;
    }
    __syncthreads();

    for (int idx = tid; idx < 4 * NWIN; idx += 128) {
        int p = idx / NWIN, kk = idx - p * NWIN;
        float d = (float)(i0 + p - 1) * (1.0f / DSCALE);
        float c = (float)(k0_s[p] + kk) * 0.1f;
        float del = d - c;
        e_s[p][kk] = expf(-10.0f * del * del);
    }
    __syncthreads();

    const float* W1l = cf_W1 + (size_t)l * KKER * FDIM;
    float b1v = cf_b1[l * FDIM + tid];
    float a0 = b1v, a1 = b1v, a2 = b1v, a3 = b1v;
    for (int kk = 0; kk < NWIN; kk++) {
        a0 += e_s[0][kk] * W1l[(k0_s[0] + kk) * FDIM + tid];
        a1 += e_s[1][kk] * W1l[(k0_s[1] + kk) * FDIM + tid];
        a2 += e_s[2][kk] * W1l[(k0_s[2] + kk) * FDIM + tid];
        a3 += e_s[3][kk] * W1l[(k0_s[3] + kk) * FDIM + tid];
    }
    w1_s[0][tid] = ssp(a0);
    w1_s[1][tid] = ssp(a1);
    w1_s[2][tid] = ssp(a2);
    w1_s[3][tid] = ssp(a3);
    __syncthreads();

    const float* W2l = cf_W2 + (size_t)l * FDIM * FDIM;
    float b2v = cf_b2[l * FDIM + tid];
    float c0 = b2v, c1 = b2v, c2 = b2v, c3 = b2v;
    for (int k = 0; k < FDIM; k++) {
        float wv = W2l[k * FDIM + tid];
        c0 += w1_s[0][k] * wv;
        c1 += w1_s[1][k] * wv;
        c2 += w1_s[2][k] * wv;
        c3 += w1_s[3][k] * wv;
    }
    g_table[l][(i0 + 0) * FDIM + tid] = ssp(c0);
    g_table[l][(i0 + 1) * FDIM + tid] = ssp(c1);
    g_table[l][(i0 + 2) * FDIM + tid] = ssp(c2);
    g_table[l][(i0 + 3) * FDIM + tid] = ssp(c3);
}

// ---------------------------------------------------------------------------
// 3) embedding gather
// ---------------------------------------------------------------------------
__global__ void embed_kernel(const int* __restrict__ x,
                             const float* __restrict__ emb) {
    g_h[blockIdx.x * FDIM + threadIdx.x] = emb[x[blockIdx.x] * FDIM + threadIdx.x];
}

// ---------------------------------------------------------------------------
// 4) generic 128->128 linear: out = [ssp](in[+in2]) @ W + b [+ res]
//    8 atoms per block, 128 threads.
// ---------------------------------------------------------------------------
__global__ __launch_bounds__(128) void lin128_kernel(
    const float* __restrict__ in, const float* __restrict__ in2,
    const float* __restrict__ W, const float* __restrict__ b,
    const float* __restrict__ res, float* __restrict__ out, int act)
{
    __shared__ float s[8][FDIM];
    int tid = threadIdx.x;
    int i0 = blockIdx.x * 8;
    for (int idx = tid; idx < 8 * FDIM; idx += 128) {
        float v = in[i0 * FDIM + idx];
        if (in2) v += in2[i0 * FDIM + idx];
        s[idx >> 7][idx & 127] = v;
    }
    __syncthreads();
    float bv = b[tid];
    float acc[8];
#pragma unroll
    for (int p = 0; p < 8; p++) acc[p] = bv;
    for (int k = 0; k < FDIM; k++) {
        float wv = W[k * FDIM + tid];
#pragma unroll
        for (int p = 0; p < 8; p++) acc[p] += s[p][k] * wv;
    }
#pragma unroll
    for (int p = 0; p < 8; p++) {
        float v = acc[p];
        if (act) v = ssp(v);
        if (res) v += res[(i0 + p) * FDIM + tid];
        out[(i0 + p) * FDIM + tid] = v;
    }
}

// ---------------------------------------------------------------------------
// 5) continuous-filter conv: c[i,f] = sum_j o[j,f] * w(d_ij)[f]
//    w via 4-point cubic Lagrange interpolation of the table.
//    Block: 4 warps (4 atoms i), j split in halves across blockIdx.y,
//    o staged in SMEM in 64-row tiles. Lane handles 4 features (float4).
// ---------------------------------------------------------------------------
__global__ __launch_bounds__(128) void conv_kernel(
    const float* __restrict__ table, float* __restrict__ cpart)
{
    __shared__ float4 osm[64][32];                // 32 KB
    int tid  = threadIdx.x;
    int warp = tid >> 5, lane = tid & 31;
    int i = blockIdx.x * 4 + warp;
    int jbase = blockIdx.y * 256;

    float4 acc = make_float4(0.f, 0.f, 0.f, 0.f);
    const float* dti = g_dt + i * NATOMS;

    for (int jt = 0; jt < 4; jt++) {
        int j0 = jbase + jt * 64;
        __syncthreads();
        float* osf = (float*)osm;
        for (int idx = tid; idx < 64 * FDIM; idx += 128)
            osf[idx] = g_o[j0 * FDIM + idx];
        __syncthreads();

        for (int jl = 0; jl < 64; jl++) {
            float t = dti[j0 + jl];
            float gf = floorf(t);
            int g = (int)gf;
            float u = t - gf;
            // cubic Lagrange weights on nodes {-1,0,1,2}
            float um1 = u - 1.0f, um2 = u - 2.0f, up1 = u + 1.0f;
            float w0 = -u * um1 * um2 * (1.0f / 6.0f);
            float w1 = up1 * um1 * um2 * 0.5f;
            float w2 = -up1 * u * um2 * 0.5f;
            float w3 = up1 * u * um1 * (1.0f / 6.0f);

            const float4* row = (const float4*)(table + (size_t)(g - 1) * FDIM);
            float4 p0 = row[lane];
            float4 p1 = row[32 + lane];
            float4 p2 = row[64 + lane];
            float4 p3 = row[96 + lane];
            float4 ov = osm[jl][lane];

            float fx = w0 * p0.x + w1 * p1.x + w2 * p2.x + w3 * p3.x;
            float fy = w0 * p0.y + w1 * p1.y + w2 * p2.y + w3 * p3.y;
            float fz = w0 * p0.z + w1 * p1.z + w2 * p2.z + w3 * p3.z;
            float fw = w0 * p0.w + w1 * p1.w + w2 * p2.w + w3 * p3.w;
            acc.x += fx * ov.x;
            acc.y += fy * ov.y;
            acc.z += fz * ov.z;
            acc.w += fw * ov.w;
        }
    }
    float4* outp = (float4*)(cpart + (size_t)blockIdx.y * NATOMS * FDIM + i * FDIM);
    outp[lane] = acc;
}

// ---------------------------------------------------------------------------
// 6) output head: out[i] = ssp(h[i]@W1 + b1) @ W2 + b2. One warp per atom.
// ---------------------------------------------------------------------------
__global__ __launch_bounds__(256) void final_kernel(
    const float* __restrict__ W1, const float* __restrict__ b1,
    const float* __restrict__ W2, const float* __restrict__ b2,
    float* __restrict__ out)
{
    int warp = threadIdx.x >> 5, lane = threadIdx.x & 31;
    int i = blockIdx.x * 8 + warp;
    const float* hi = g_h + i * FDIM;
    float acc = b1[lane];
    for (int k = 0; k < FDIM; k++)
        acc += hi[k] * W1[k * 32 + lane];
    float v = ssp(acc) * W2[lane];
#pragma unroll
    for (int off = 16; off; off >>= 1)
        v += __shfl_xor_sync(0xffffffffu, v, off);
    if (lane == 0) out[i] = v + b2[0];
}

// ---------------------------------------------------------------------------
extern "C" void kernel_launch(void* const* d_in, const int* in_sizes, int n_in,
                              void* d_out, int out_size) {
    const int*   x      = (const int*)  d_in[0];
    const float* r      = (const float*)d_in[1];
    const float* emb    = (const float*)d_in[2];
    const float* aw_W   = (const float*)d_in[3];
    const float* aw_b   = (const float*)d_in[4];
    const float* cf_W1  = (const float*)d_in[5];
    const float* cf_b1  = (const float*)d_in[6];
    const float* cf_W2  = (const float*)d_in[7];
    const float* cf_b2  = (const float*)d_in[8];
    const float* n_W1   = (const float*)d_in[9];
    const float* n_b1   = (const float*)d_in[10];
    const float* n_W2   = (const float*)d_in[11];
    const float* n_b2   = (const float*)d_in[12];
    const float* out_W1 = (const float*)d_in[13];
    const float* out_b1 = (const float*)d_in[14];
    const float* out_W2 = (const float*)d_in[15];
    const float* out_b2 = (const float*)d_in[16];

    float *p_table, *p_h, *p_o, *p_cpart, *p_c1;
    cudaGetSymbolAddress((void**)&p_table, g_table);
    cudaGetSymbolAddress((void**)&p_h,     g_h);
    cudaGetSymbolAddress((void**)&p_o,     g_o);
    cudaGetSymbolAddress((void**)&p_cpart, g_cpart);
    cudaGetSymbolAddress((void**)&p_c1,    g_c1);

    dist_kernel<<<(NATOMS * NATOMS) / 256, 256>>>(r);
    table_kernel<<<dim3(NGRID / 4, NLAY), 128>>>(cf_W1, cf_b1, cf_W2, cf_b2);
    embed_kernel<<<NATOMS, FDIM>>>(x, emb);

    for (int l = 0; l < NLAY; l++) {
        // o = h @ aw_W[l] + aw_b[l]
        lin128_kernel<<<NATOMS / 8, 128>>>(p_h, nullptr,
            aw_W + (size_t)l * FDIM * FDIM, aw_b + l * FDIM,
            nullptr, p_o, 0);
        // conv with tabulated filters
        conv_kernel<<<dim3(NATOMS / 4, 2), 128>>>(
            p_table + (size_t)l * NGRID * FDIM, p_cpart);
        // c1 = ssp((cpart0+cpart1) @ n_W1[l] + n_b1[l])
        lin128_kernel<<<NATOMS / 8, 128>>>(p_cpart, p_cpart + NATOMS * FDIM,
            n_W1 + (size_t)l * FDIM * FDIM, n_b1 + l * FDIM,
            nullptr, p_c1, 1);
        // h = h + c1 @ n_W2[l] + n_b2[l]
        lin128_kernel<<<NATOMS / 8, 128>>>(p_c1, nullptr,
            n_W2 + (size_t)l * FDIM * FDIM, n_b2 + l * FDIM,
            p_h, p_h, 0);
    }
    final_kernel<<<NATOMS / 8, 256>>>(out_W1, out_b1, out_W2, out_b2,
                                      (float*)d_out);
}

// round 2
// speedup vs baseline: 1.9211x; 1.9211x over previous
#include <cuda_runtime.h>
#include <cuda_fp16.h>
#include <math.h>
#include <string.h>

// ---------------------------------------------------------------------------
// SchNet on GB300, round 2.
// - filter MLP tabulated on d-grid (cubic Lagrange, h=1/32), table in fp16
// - per-pair interp weights precomputed once (packed 4x half + ushort g)
// - conv + n-MLP(+residual) fused in one kernel; o staged fully in smem (fp16)
// - atom-wise linear: split-K, 1024 warps
// ---------------------------------------------------------------------------

#define NATOMS 512
#define FDIM   128
#define KKER   301
#define NLAY   3
#define NGRID  576
#define DSCALE 32.0f
#define NWIN   48
#define LOG2F_ 0.6931471805599453f

// scratch (static device globals; no allocations anywhere)
__device__ uint2          g_w4[NATOMS * NATOMS];   // packed half w0..w3
__device__ unsigned short g_gi[NATOMS * NATOMS];   // grid index g
__device__ __half         g_tab[NLAY][NGRID * FDIM];
__device__ float          g_h[NATOMS * FDIM];
__device__ __half         g_oh[NATOMS * FDIM];     // o in fp16 for conv

__device__ __forceinline__ float ssp(float x) {
    float ax = fabsf(x);
    return fmaxf(x, 0.0f) + log1pf(expf(-ax)) - LOG2F_;
}

__device__ __forceinline__ __half2 u2h(unsigned u) {
    __half2 h; memcpy(&h, &u, 4); return h;
}

// ---------------------------------------------------------------------------
// 1) prep: pairwise distances -> packed interp weights; plus embedding gather
//    blocks [0,1024): dist; blocks [1024,1280): embed
// ---------------------------------------------------------------------------
__global__ __launch_bounds__(256) void prep_kernel(
    const float* __restrict__ r, const int* __restrict__ x,
    const float* __restrict__ emb)
{
    if (blockIdx.x < 1024) {
        int idx = blockIdx.x * 256 + threadIdx.x;     // N*N pairs
        int i = idx >> 9, j = idx & 511;
        float dx = r[i * 3 + 0] - r[j * 3 + 0];
        float dy = r[i * 3 + 1] - r[j * 3 + 1];
        float dz = r[i * 3 + 2] - r[j * 3 + 2];
        float d = sqrtf(dx * dx + dy * dy + dz * dz);
        float t = fminf(d * DSCALE + 1.0f, (float)(NGRID - 4) + 0.999f);
        float gf = floorf(t);
        int   g  = (int)gf;
        float u  = t - gf;
        float um1 = u - 1.0f, um2 = u - 2.0f, up1 = u + 1.0f;
        float w0 = -u * um1 * um2 * (1.0f / 6.0f);
        float w1 = up1 * um1 * um2 * 0.5f;
        float w2 = -up1 * u * um2 * 0.5f;
        float w3 = up1 * u * um1 * (1.0f / 6.0f);
        __half2 h01 = __floats2half2_rn(w0, w1);
        __half2 h23 = __floats2half2_rn(w2, w3);
        uint2 pk;
        memcpy(&pk.x, &h01, 4);
        memcpy(&pk.y, &h23, 4);
        g_w4[idx] = pk;
        g_gi[idx] = (unsigned short)g;
    } else {
        int idx = (blockIdx.x - 1024) * 256 + threadIdx.x;  // N*F elements
        int a = idx >> 7;
        g_h[idx] = emb[x[a] * FDIM + (idx & 127)];
    }
}

// ---------------------------------------------------------------------------
// 2) filter tables (fp16 output). 4 grid points / block, 128 threads.
// ---------------------------------------------------------------------------
__global__ __launch_bounds__(128) void table_kernel(
    const float* __restrict__ cf_W1, const float* __restrict__ cf_b1,
    const float* __restrict__ cf_W2, const float* __restrict__ cf_b2)
{
    int l  = blockIdx.y;
    int i0 = blockIdx.x * 4;
    int tid = threadIdx.x;

    __shared__ float e_s[4][NWIN];
    __shared__ int   k0_s[4];
    __shared__ float w1_s[4][FDIM];

    if (tid < 4) {
        float d = (float)(i0 + tid - 1) * (1.0f / DSCALE);
        int k0 = (int)ceilf((d - 2.0f) * 10.0f);
        k0 = max(0, min(KKER - NWIN, k0));
        k0_s[tid] = k0;
    }
    __syncthreads();

    for (int idx = tid; idx < 4 * NWIN; idx += 128) {
        int p = idx / NWIN, kk = idx - p * NWIN;
        float d = (float)(i0 + p - 1) * (1.0f / DSCALE);
        float c = (float)(k0_s[p] + kk) * 0.1f;
        float del = d - c;
        e_s[p][kk] = expf(-10.0f * del * del);
    }
    __syncthreads();

    const float* W1l = cf_W1 + (size_t)l * KKER * FDIM;
    float b1v = cf_b1[l * FDIM + tid];
    float a0 = b1v, a1 = b1v, a2 = b1v, a3 = b1v;
    for (int kk = 0; kk < NWIN; kk++) {
        a0 += e_s[0][kk] * W1l[(k0_s[0] + kk) * FDIM + tid];
        a1 += e_s[1][kk] * W1l[(k0_s[1] + kk) * FDIM + tid];
        a2 += e_s[2][kk] * W1l[(k0_s[2] + kk) * FDIM + tid];
        a3 += e_s[3][kk] * W1l[(k0_s[3] + kk) * FDIM + tid];
    }
    w1_s[0][tid] = ssp(a0);
    w1_s[1][tid] = ssp(a1);
    w1_s[2][tid] = ssp(a2);
    w1_s[3][tid] = ssp(a3);
    __syncthreads();

    const float* W2l = cf_W2 + (size_t)l * FDIM * FDIM;
    float b2v = cf_b2[l * FDIM + tid];
    float c0 = b2v, c1 = b2v, c2 = b2v, c3 = b2v;
    for (int k = 0; k < FDIM; k++) {
        float wv = W2l[k * FDIM + tid];
        c0 += w1_s[0][k] * wv;
        c1 += w1_s[1][k] * wv;
        c2 += w1_s[2][k] * wv;
        c3 += w1_s[3][k] * wv;
    }
    g_tab[l][(i0 + 0) * FDIM + tid] = __float2half_rn(ssp(c0));
    g_tab[l][(i0 + 1) * FDIM + tid] = __float2half_rn(ssp(c1));
    g_tab[l][(i0 + 2) * FDIM + tid] = __float2half_rn(ssp(c2));
    g_tab[l][(i0 + 3) * FDIM + tid] = __float2half_rn(ssp(c3));
}

// ---------------------------------------------------------------------------
// 3) atom-wise linear: o = h @ W + b (fp32 compute, fp16 store).
//    128 blocks x 256 thr; 4 atoms/block; 2 warps per atom split K.
// ---------------------------------------------------------------------------
__global__ __launch_bounds__(256) void aw_kernel(
    const float* __restrict__ W, const float* __restrict__ b)
{
    __shared__ float h_sh[4][FDIM];
    __shared__ float part[8][FDIM];
    int tid = threadIdx.x;
    int i0 = blockIdx.x * 4;
    for (int idx = tid; idx < 4 * FDIM; idx += 256)
        h_sh[idx >> 7][idx & 127] = g_h[i0 * FDIM + idx];
    __syncthreads();

    int w = tid >> 5, lane = tid & 31;
    int a = w >> 1, kh = w & 1;
    const float4* Wr = (const float4*)W;
    float4 acc = make_float4(0.f, 0.f, 0.f, 0.f);
    int kbase = kh * 64;
#pragma unroll 8
    for (int kk = 0; kk < 64; kk++) {
        int k = kbase + kk;
        float4 wv = Wr[k * 32 + lane];
        float hv = h_sh[a][k];
        acc.x += hv * wv.x;
        acc.y += hv * wv.y;
        acc.z += hv * wv.z;
        acc.w += hv * wv.w;
    }
    ((float4*)part[w])[lane] = acc;
    __syncthreads();

    for (int idx = tid; idx < 4 * FDIM; idx += 256) {
        int a2 = idx >> 7, f = idx & 127;
        float v = part[2 * a2][f] + part[2 * a2 + 1][f] + b[f];
        g_oh[(i0 + a2) * FDIM + f] = __float2half_rn(v);
    }
}

// ---------------------------------------------------------------------------
// 4) fused conv + n-MLP + residual. 128 blocks x 256 thr, 4 atoms/block,
//    2 warps per atom split j. o fully staged in smem (fp16, 128 KB).
// ---------------------------------------------------------------------------
#define CS_O    0
#define CS_W4   131072
#define CS_GI   147456
#define CS_PART 151552
#define CS_C    155648
#define CS_C1   157696
#define CS_TOT  159744

__global__ __launch_bounds__(256) void conv_fused_kernel(
    const __half* __restrict__ tab,
    const float* __restrict__ nW1, const float* __restrict__ nb1,
    const float* __restrict__ nW2, const float* __restrict__ nb2)
{
    extern __shared__ char cs[];
    __half*         o_sh  = (__half*)(cs + CS_O);
    uint2*          w4_sh = (uint2*)(cs + CS_W4);
    unsigned short* gi_sh = (unsigned short*)(cs + CS_GI);
    float*          part  = (float*)(cs + CS_PART);
    float*          c_sh  = (float*)(cs + CS_C);
    float*          c1_sh = (float*)(cs + CS_C1);

    int tid = threadIdx.x;
    int i0 = blockIdx.x * 4;

    // stage o (all 512 rows, fp16)
    {
        const uint4* src = (const uint4*)g_oh;
        uint4* dst = (uint4*)o_sh;
        for (int idx = tid; idx < NATOMS * FDIM * 2 / 16; idx += 256)
            dst[idx] = src[idx];
    }
    // stage per-pair weights for this block's 4 atoms
    for (int idx = tid; idx < 4 * NATOMS; idx += 256) {
        int a = idx >> 9, j = idx & 511;
        w4_sh[idx] = g_w4[(i0 + a) * NATOMS + j];
        gi_sh[idx] = g_gi[(i0 + a) * NATOMS + j];
    }
    __syncthreads();

    int w = tid >> 5, lane = tid & 31;
    int a = w >> 1, hh = w & 1;
    const uint2* w4row = w4_sh + a * NATOMS;
    const unsigned short* girow = gi_sh + a * NATOMS;

    float4 acc = make_float4(0.f, 0.f, 0.f, 0.f);
    int jbase = hh * 256;
#pragma unroll 2
    for (int jj = 0; jj < 256; jj++) {
        int j = jbase + jj;
        uint2 wp = w4row[j];
        int   g  = girow[j];
        __half2 hA = u2h(wp.x), hB = u2h(wp.y);
        __half2 w0 = __half2half2(__low2half(hA));
        __half2 w1 = __half2half2(__high2half(hA));
        __half2 w2 = __half2half2(__low2half(hB));
        __half2 w3 = __half2half2(__high2half(hB));

        const uint2* trow = (const uint2*)(tab + (size_t)(g - 1) * FDIM);
        uint2 q0 = trow[lane];
        uint2 q1 = trow[32 + lane];
        uint2 q2 = trow[64 + lane];
        uint2 q3 = trow[96 + lane];
        uint2 ov = ((const uint2*)(o_sh + j * FDIM))[lane];

        __half2 fA = __hmul2(w0, u2h(q0.x));
        fA = __hfma2(w1, u2h(q1.x), fA);
        fA = __hfma2(w2, u2h(q2.x), fA);
        fA = __hfma2(w3, u2h(q3.x), fA);
        __half2 pA = __hmul2(fA, u2h(ov.x));
        float2 fpA = __half22float2(pA);
        acc.x += fpA.x;
        acc.y += fpA.y;

        __half2 fB = __hmul2(w0, u2h(q0.y));
        fB = __hfma2(w1, u2h(q1.y), fB);
        fB = __hfma2(w2, u2h(q2.y), fB);
        fB = __hfma2(w3, u2h(q3.y), fB);
        __half2 pB = __hmul2(fB, u2h(ov.y));
        float2 fpB = __half22float2(pB);
        acc.z += fpB.x;
        acc.w += fpB.y;
    }
    ((float4*)(part + w * FDIM))[lane] = acc;
    __syncthreads();

    // combine j-halves: c[a][f]
    for (int idx = tid; idx < 4 * FDIM; idx += 256) {
        int a2 = idx >> 7, f = idx & 127;
        c_sh[idx] = part[(2 * a2) * FDIM + f] + part[(2 * a2 + 1) * FDIM + f];
    }
    __syncthreads();

    // n1: c1 = ssp(c @ W1 + b1)    (thread handles atoms ap and ap+2, feat f)
    int f = tid & 127, ap = tid >> 7;
    {
        float acc0 = nb1[f], acc1 = acc0;
        const float* r0 = c_sh + ap * FDIM;
        const float* r1 = c_sh + (ap + 2) * FDIM;
#pragma unroll 8
        for (int k = 0; k < FDIM; k++) {
            float wv = nW1[k * FDIM + f];
            acc0 += r0[k] * wv;
            acc1 += r1[k] * wv;
        }
        c1_sh[ap * FDIM + f] = ssp(acc0);
        c1_sh[(ap + 2) * FDIM + f] = ssp(acc1);
    }
    __syncthreads();

    // n2 + residual: h += c1 @ W2 + b2
    {
        float acc0 = nb2[f], acc1 = acc0;
        const float* r0 = c1_sh + ap * FDIM;
        const float* r1 = c1_sh + (ap + 2) * FDIM;
#pragma unroll 8
        for (int k = 0; k < FDIM; k++) {
            float wv = nW2[k * FDIM + f];
            acc0 += r0[k] * wv;
            acc1 += r1[k] * wv;
        }
        g_h[(i0 + ap) * FDIM + f]     += acc0;
        g_h[(i0 + ap + 2) * FDIM + f] += acc1;
    }
}

// ---------------------------------------------------------------------------
// 5) output head: one warp per atom
// ---------------------------------------------------------------------------
__global__ __launch_bounds__(256) void final_kernel(
    const float* __restrict__ W1, const float* __restrict__ b1,
    const float* __restrict__ W2, const float* __restrict__ b2,
    float* __restrict__ out)
{
    int warp = threadIdx.x >> 5, lane = threadIdx.x & 31;
    int i = blockIdx.x * 8 + warp;
    const float* hi = g_h + i * FDIM;
    float acc = b1[lane];
#pragma unroll 8
    for (int k = 0; k < FDIM; k++)
        acc += hi[k] * W1[k * 32 + lane];
    float v = ssp(acc) * W2[lane];
#pragma unroll
    for (int off = 16; off; off >>= 1)
        v += __shfl_xor_sync(0xffffffffu, v, off);
    if (lane == 0) out[i] = v + b2[0];
}

// ---------------------------------------------------------------------------
extern "C" void kernel_launch(void* const* d_in, const int* in_sizes, int n_in,
                              void* d_out, int out_size) {
    const int*   x      = (const int*)  d_in[0];
    const float* r      = (const float*)d_in[1];
    const float* emb    = (const float*)d_in[2];
    const float* aw_W   = (const float*)d_in[3];
    const float* aw_b   = (const float*)d_in[4];
    const float* cf_W1  = (const float*)d_in[5];
    const float* cf_b1  = (const float*)d_in[6];
    const float* cf_W2  = (const float*)d_in[7];
    const float* cf_b2  = (const float*)d_in[8];
    const float* n_W1   = (const float*)d_in[9];
    const float* n_b1   = (const float*)d_in[10];
    const float* n_W2   = (const float*)d_in[11];
    const float* n_b2   = (const float*)d_in[12];
    const float* out_W1 = (const float*)d_in[13];
    const float* out_b1 = (const float*)d_in[14];
    const float* out_W2 = (const float*)d_in[15];
    const float* out_b2 = (const float*)d_in[16];

    __half* p_tab;
    cudaGetSymbolAddress((void**)&p_tab, g_tab);

    cudaFuncSetAttribute(conv_fused_kernel,
                         cudaFuncAttributeMaxDynamicSharedMemorySize, CS_TOT);

    prep_kernel<<<1280, 256>>>(r, x, emb);
    table_kernel<<<dim3(NGRID / 4, NLAY), 128>>>(cf_W1, cf_b1, cf_W2, cf_b2);

    for (int l = 0; l < NLAY; l++) {
        aw_kernel<<<NATOMS / 4, 256>>>(aw_W + (size_t)l * FDIM * FDIM,
                                       aw_b + l * FDIM);
        conv_fused_kernel<<<NATOMS / 4, 256, CS_TOT>>>(
            p_tab + (size_t)l * NGRID * FDIM,
            n_W1 + (size_t)l * FDIM * FDIM, n_b1 + l * FDIM,
            n_W2 + (size_t)l * FDIM * FDIM, n_b2 + l * FDIM);
    }
    final_kernel<<<NATOMS / 8, 256>>>(out_W1, out_b1, out_W2, out_b2,
                                      (float*)d_out);
}

// round 4
// speedup vs baseline: 2.6303x; 1.3692x over previous
#include <cuda_runtime.h>
#include <cuda_fp16.h>
#include <math.h>
#include <string.h>

// ---------------------------------------------------------------------------
// SchNet on GB300, round 4 (round-3 design, smem trimmed + overlap reuse).
// - filter MLP tabulated on d-grid (cubic Lagrange, h=1/32), table in fp16
// - per-pair interp weights precomputed once (uint4: 4x half + grid idx)
// - conv: filter TABLE staged in SMEM; o staged in smem j-tiles;
//   16 warps/block (4 atoms x 4-way j split)
// - conv + n-MLP + residual fused; scratch regions (part/c/c1) alias the
//   o-tile buffer, which is dead after the conv mainloop.
// ---------------------------------------------------------------------------

#define NATOMS 512
#define FDIM   128
#define KKER   301
#define NLAY   3
#define NGRID  576
#define DSCALE 32.0f
#define NWIN   48
#define LOG2F_ 0.6931471805599453f

// scratch (static device globals; no allocations anywhere)
__device__ uint4  g_meta[NATOMS * NATOMS];     // w0..w3 (half) + grid idx
__device__ __half g_tab[NLAY][NGRID * FDIM];
__device__ float  g_h[NATOMS * FDIM];
__device__ __half g_oh[NATOMS * FDIM];

__device__ __forceinline__ float ssp(float x) {
    float ax = fabsf(x);
    return fmaxf(x, 0.0f) + log1pf(expf(-ax)) - LOG2F_;
}

__device__ __forceinline__ __half2 u2h(unsigned u) {
    __half2 h; memcpy(&h, &u, 4); return h;
}

// ---------------------------------------------------------------------------
// 1) prep: pairwise distances -> packed interp meta; plus embedding gather
// ---------------------------------------------------------------------------
__global__ __launch_bounds__(256) void prep_kernel(
    const float* __restrict__ r, const int* __restrict__ x,
    const float* __restrict__ emb)
{
    if (blockIdx.x < 1024) {
        int idx = blockIdx.x * 256 + threadIdx.x;     // N*N pairs
        int i = idx >> 9, j = idx & 511;
        float dx = r[i * 3 + 0] - r[j * 3 + 0];
        float dy = r[i * 3 + 1] - r[j * 3 + 1];
        float dz = r[i * 3 + 2] - r[j * 3 + 2];
        float d = sqrtf(dx * dx + dy * dy + dz * dz);
        float t = fminf(d * DSCALE + 1.0f, (float)(NGRID - 4) + 0.999f);
        float gf = floorf(t);
        int   g  = (int)gf;
        float u  = t - gf;
        float um1 = u - 1.0f, um2 = u - 2.0f, up1 = u + 1.0f;
        float w0 = -u * um1 * um2 * (1.0f / 6.0f);
        float w1 = up1 * um1 * um2 * 0.5f;
        float w2 = -up1 * u * um2 * 0.5f;
        float w3 = up1 * u * um1 * (1.0f / 6.0f);
        __half2 h01 = __floats2half2_rn(w0, w1);
        __half2 h23 = __floats2half2_rn(w2, w3);
        uint4 pk;
        memcpy(&pk.x, &h01, 4);
        memcpy(&pk.y, &h23, 4);
        pk.z = (unsigned)g;
        pk.w = 0;
        g_meta[idx] = pk;
    } else {
        int idx = (blockIdx.x - 1024) * 256 + threadIdx.x;  // N*F elements
        int a = idx >> 7;
        g_h[idx] = emb[x[a] * FDIM + (idx & 127)];
    }
}

// ---------------------------------------------------------------------------
// 2) filter tables (fp16 output). 4 grid points / block, 128 threads.
// ---------------------------------------------------------------------------
__global__ __launch_bounds__(128) void table_kernel(
    const float* __restrict__ cf_W1, const float* __restrict__ cf_b1,
    const float* __restrict__ cf_W2, const float* __restrict__ cf_b2)
{
    int l  = blockIdx.y;
    int i0 = blockIdx.x * 4;
    int tid = threadIdx.x;

    __shared__ float e_s[4][NWIN];
    __shared__ int   k0_s[4];
    __shared__ float w1_s[4][FDIM];

    if (tid < 4) {
        float d = (float)(i0 + tid - 1) * (1.0f / DSCALE);
        int k0 = (int)ceilf((d - 2.0f) * 10.0f);
        k0 = max(0, min(KKER - NWIN, k0));
        k0_s[tid] = k0;
    }
    __syncthreads();

    for (int idx = tid; idx < 4 * NWIN; idx += 128) {
        int p = idx / NWIN, kk = idx - p * NWIN;
        float d = (float)(i0 + p - 1) * (1.0f / DSCALE);
        float c = (float)(k0_s[p] + kk) * 0.1f;
        float del = d - c;
        e_s[p][kk] = expf(-10.0f * del * del);
    }
    __syncthreads();

    const float* W1l = cf_W1 + (size_t)l * KKER * FDIM;
    float b1v = cf_b1[l * FDIM + tid];
    float a0 = b1v, a1 = b1v, a2 = b1v, a3 = b1v;
    for (int kk = 0; kk < NWIN; kk++) {
        a0 += e_s[0][kk] * W1l[(k0_s[0] + kk) * FDIM + tid];
        a1 += e_s[1][kk] * W1l[(k0_s[1] + kk) * FDIM + tid];
        a2 += e_s[2][kk] * W1l[(k0_s[2] + kk) * FDIM + tid];
        a3 += e_s[3][kk] * W1l[(k0_s[3] + kk) * FDIM + tid];
    }
    w1_s[0][tid] = ssp(a0);
    w1_s[1][tid] = ssp(a1);
    w1_s[2][tid] = ssp(a2);
    w1_s[3][tid] = ssp(a3);
    __syncthreads();

    const float* W2l = cf_W2 + (size_t)l * FDIM * FDIM;
    float b2v = cf_b2[l * FDIM + tid];
    float c0 = b2v, c1 = b2v, c2 = b2v, c3 = b2v;
    for (int k = 0; k < FDIM; k++) {
        float wv = W2l[k * FDIM + tid];
        c0 += w1_s[0][k] * wv;
        c1 += w1_s[1][k] * wv;
        c2 += w1_s[2][k] * wv;
        c3 += w1_s[3][k] * wv;
    }
    g_tab[l][(i0 + 0) * FDIM + tid] = __float2half_rn(ssp(c0));
    g_tab[l][(i0 + 1) * FDIM + tid] = __float2half_rn(ssp(c1));
    g_tab[l][(i0 + 2) * FDIM + tid] = __float2half_rn(ssp(c2));
    g_tab[l][(i0 + 3) * FDIM + tid] = __float2half_rn(ssp(c3));
}

// ---------------------------------------------------------------------------
// 3) atom-wise linear: o = h @ W + b (fp32 compute, fp16 store).
// ---------------------------------------------------------------------------
__global__ __launch_bounds__(256) void aw_kernel(
    const float* __restrict__ W, const float* __restrict__ b)
{
    __shared__ float h_sh[4][FDIM];
    __shared__ float part[8][FDIM];
    int tid = threadIdx.x;
    int i0 = blockIdx.x * 4;
    for (int idx = tid; idx < 4 * FDIM; idx += 256)
        h_sh[idx >> 7][idx & 127] = g_h[i0 * FDIM + idx];
    __syncthreads();

    int w = tid >> 5, lane = tid & 31;
    int a = w >> 1, kh = w & 1;
    const float4* Wr = (const float4*)W;
    float4 acc = make_float4(0.f, 0.f, 0.f, 0.f);
    int kbase = kh * 64;
#pragma unroll 8
    for (int kk = 0; kk < 64; kk++) {
        int k = kbase + kk;
        float4 wv = Wr[k * 32 + lane];
        float hv = h_sh[a][k];
        acc.x += hv * wv.x;
        acc.y += hv * wv.y;
        acc.z += hv * wv.z;
        acc.w += hv * wv.w;
    }
    ((float4*)part[w])[lane] = acc;
    __syncthreads();

    for (int idx = tid; idx < 4 * FDIM; idx += 256) {
        int a2 = idx >> 7, f = idx & 127;
        float v = part[2 * a2][f] + part[2 * a2 + 1][f] + b[f];
        g_oh[(i0 + a2) * FDIM + f] = __float2half_rn(v);
    }
}

// ---------------------------------------------------------------------------
// 4) fused conv + n-MLP + residual. 128 blocks x 512 thr.
//    4 atoms/block, 4-way j split; table fully in smem, o in 128-j tiles.
//    part/c/c1 alias the o-tile region (dead after conv mainloop).
//    Layout (bytes):
//      [0,147456)           tab_s   (576*128 half)
//      [147456,180224)      meta    (2048 uint4)
//      [180224,213000)      o_t     (128*128 half = 32768)  } aliased:
//        part: 16*128 float = 8192   @ 180224
//        c   :  4*128 float = 2048   @ 188416
//        c1  :  4*128 float = 2048   @ 190464
//    total = 212992 B (safely under 232448 cap)
// ---------------------------------------------------------------------------
#define CS_TAB  0
#define CS_META 147456
#define CS_OT   180224
#define CS_TOT  212992

__global__ __launch_bounds__(512) void conv_fused_kernel(
    const __half* __restrict__ tab,
    const float* __restrict__ nW1, const float* __restrict__ nb1,
    const float* __restrict__ nW2, const float* __restrict__ nb2)
{
    extern __shared__ char cs[];
    __half* tab_s = (__half*)(cs + CS_TAB);
    uint4*  meta  = (uint4*)(cs + CS_META);
    __half* o_t   = (__half*)(cs + CS_OT);
    float*  part  = (float*)(cs + CS_OT);            // alias (after conv)
    float*  c_sh  = (float*)(cs + CS_OT + 8192);     // alias
    float*  c1_sh = (float*)(cs + CS_OT + 10240);    // alias

    int tid = threadIdx.x;
    int i0 = blockIdx.x * 4;

    // stage full filter table (144 KB)
    {
        const uint4* src = (const uint4*)tab;
        uint4* dst = (uint4*)tab_s;
#pragma unroll
        for (int k = 0; k < 18; k++)
            dst[tid + 512 * k] = src[tid + 512 * k];
    }
    // stage per-pair meta for this block's 4 atoms (32 KB)
    {
        const uint4* src = g_meta + (size_t)i0 * NATOMS;
#pragma unroll
        for (int k = 0; k < 4; k++)
            meta[tid + 512 * k] = src[tid + 512 * k];
    }

    int w = tid >> 5, lane = tid & 31;
    int a = w >> 2, q = w & 3;
    const uint4* mrow = meta + a * NATOMS;

    float4 acc = make_float4(0.f, 0.f, 0.f, 0.f);
#pragma unroll
    for (int jt = 0; jt < 4; jt++) {
        int j0 = jt * 128;
        __syncthreads();                 // o_t reuse barrier (also covers staging)
        {
            const uint4* src = (const uint4*)(g_oh + (size_t)j0 * FDIM);
            uint4* dst = (uint4*)o_t;
#pragma unroll
            for (int k = 0; k < 4; k++)
                dst[tid + 512 * k] = src[tid + 512 * k];
        }
        __syncthreads();

        int jl0 = q * 32;
#pragma unroll 4
        for (int jj = 0; jj < 32; jj++) {
            int jl = jl0 + jj;
            uint4 m = mrow[j0 + jl];
            int g = (int)m.z;
            __half2 hA = u2h(m.x), hB = u2h(m.y);
            __half2 w0 = __half2half2(__low2half(hA));
            __half2 w1 = __half2half2(__high2half(hA));
            __half2 w2 = __half2half2(__low2half(hB));
            __half2 w3 = __half2half2(__high2half(hB));

            const uint2* trow = (const uint2*)(tab_s + (g - 1) * FDIM);
            uint2 q0 = trow[lane];
            uint2 q1 = trow[32 + lane];
            uint2 q2 = trow[64 + lane];
            uint2 q3 = trow[96 + lane];
            uint2 ov = ((const uint2*)(o_t + jl * FDIM))[lane];

            __half2 fA = __hmul2(w0, u2h(q0.x));
            fA = __hfma2(w1, u2h(q1.x), fA);
            fA = __hfma2(w2, u2h(q2.x), fA);
            fA = __hfma2(w3, u2h(q3.x), fA);
            __half2 pA = __hmul2(fA, u2h(ov.x));
            float2 fpA = __half22float2(pA);
            acc.x += fpA.x;
            acc.y += fpA.y;

            __half2 fB = __hmul2(w0, u2h(q0.y));
            fB = __hfma2(w1, u2h(q1.y), fB);
            fB = __hfma2(w2, u2h(q2.y), fB);
            fB = __hfma2(w3, u2h(q3.y), fB);
            __half2 pB = __hmul2(fB, u2h(ov.y));
            float2 fpB = __half22float2(pB);
            acc.z += fpB.x;
            acc.w += fpB.y;
        }
    }
    __syncthreads();                     // o_t dead; part aliases it now
    ((float4*)(part + w * FDIM))[lane] = acc;
    __syncthreads();

    // combine 4 j-splits: c[a][f]  (compute into regs, then barrier, then store:
    // c_sh aliases nothing live — it sits past part[16*128]? No: part is 16*128
    // floats = 8192 B at CS_OT, c_sh at CS_OT+8192 — disjoint. Safe.)
    {
        int a2 = tid >> 7, f = tid & 127;
        c_sh[tid] = part[(a2 * 4 + 0) * FDIM + f] + part[(a2 * 4 + 1) * FDIM + f]
                  + part[(a2 * 4 + 2) * FDIM + f] + part[(a2 * 4 + 3) * FDIM + f];
    }
    __syncthreads();

    int f = tid & 127, ap = tid >> 7;
    // n1: c1 = ssp(c @ W1 + b1)
    {
        float acc0 = nb1[f];
        const float* r0 = c_sh + ap * FDIM;
#pragma unroll 8
        for (int k = 0; k < FDIM; k++)
            acc0 += r0[k] * nW1[k * FDIM + f];
        c1_sh[ap * FDIM + f] = ssp(acc0);
    }
    __syncthreads();

    // n2 + residual: h += c1 @ W2 + b2
    {
        float acc0 = nb2[f];
        const float* r0 = c1_sh + ap * FDIM;
#pragma unroll 8
        for (int k = 0; k < FDIM; k++)
            acc0 += r0[k] * nW2[k * FDIM + f];
        g_h[(i0 + ap) * FDIM + f] += acc0;
    }
}

// ---------------------------------------------------------------------------
// 5) output head: one warp per atom
// ---------------------------------------------------------------------------
__global__ __launch_bounds__(256) void final_kernel(
    const float* __restrict__ W1, const float* __restrict__ b1,
    const float* __restrict__ W2, const float* __restrict__ b2,
    float* __restrict__ out)
{
    int warp = threadIdx.x >> 5, lane = threadIdx.x & 31;
    int i = blockIdx.x * 8 + warp;
    const float* hi = g_h + i * FDIM;
    float acc = b1[lane];
#pragma unroll 8
    for (int k = 0; k < FDIM; k++)
        acc += hi[k] * W1[k * 32 + lane];
    float v = ssp(acc) * W2[lane];
#pragma unroll
    for (int off = 16; off; off >>= 1)
        v += __shfl_xor_sync(0xffffffffu, v, off);
    if (lane == 0) out[i] = v + b2[0];
}

// ---------------------------------------------------------------------------
extern "C" void kernel_launch(void* const* d_in, const int* in_sizes, int n_in,
                              void* d_out, int out_size) {
    const int*   x      = (const int*)  d_in[0];
    const float* r      = (const float*)d_in[1];
    const float* emb    = (const float*)d_in[2];
    const float* aw_W   = (const float*)d_in[3];
    const float* aw_b   = (const float*)d_in[4];
    const float* cf_W1  = (const float*)d_in[5];
    const float* cf_b1  = (const float*)d_in[6];
    const float* cf_W2  = (const float*)d_in[7];
    const float* cf_b2  = (const float*)d_in[8];
    const float* n_W1   = (const float*)d_in[9];
    const float* n_b1   = (const float*)d_in[10];
    const float* n_W2   = (const float*)d_in[11];
    const float* n_b2   = (const float*)d_in[12];
    const float* out_W1 = (const float*)d_in[13];
    const float* out_b1 = (const float*)d_in[14];
    const float* out_W2 = (const float*)d_in[15];
    const float* out_b2 = (const float*)d_in[16];

    __half* p_tab;
    cudaGetSymbolAddress((void**)&p_tab, g_tab);

    cudaFuncSetAttribute(conv_fused_kernel,
                         cudaFuncAttributeMaxDynamicSharedMemorySize, CS_TOT);

    prep_kernel<<<1280, 256>>>(r, x, emb);
    table_kernel<<<dim3(NGRID / 4, NLAY), 128>>>(cf_W1, cf_b1, cf_W2, cf_b2);

    for (int l = 0; l < NLAY; l++) {
        aw_kernel<<<NATOMS / 4, 256>>>(aw_W + (size_t)l * FDIM * FDIM,
                                       aw_b + l * FDIM);
        conv_fused_kernel<<<NATOMS / 4, 512, CS_TOT>>>(
            p_tab + (size_t)l * NGRID * FDIM,
            n_W1 + (size_t)l * FDIM * FDIM, n_b1 + l * FDIM,
            n_W2 + (size_t)l * FDIM * FDIM, n_b2 + l * FDIM);
    }
    final_kernel<<<NATOMS / 8, 256>>>(out_W1, out_b1, out_W2, out_b2,
                                      (float*)d_out);
}